// round 1
// baseline (speedup 1.0000x reference)
#include <cuda_runtime.h>
#include <cuda_bf16.h>
#include <math.h>

// ElevationSConvResidualEncoder — GB300 sm_103a
//
// Key observation (dead-code elimination, input-independent):
//   In the reference ConvLSTM step:
//       mem = sigmoid(o) * tanh(syn)
//   sigmoid() in (0,1], |tanh()| <= 1  =>  exact product <= 1, and fl(a*b) <= 1.0f
//   (1.0 is representable; round-to-nearest of a value <= 1 cannot exceed 1).
//   spike = (mem - 1.0 > 0) is therefore ALWAYS false (also false for NaN).
//   => spikes == 0 everywhere => pooled == 0 => residual == proj_b
//   => e_lat = relu(relu(elev @ We^T + be) + 0.4*sigmoid(gain) * proj_b)
//
// So the output is exactly:
//   out[0] = relu(distance  @ Wd^T + bd)           [8,512]
//   out[1] = relu(azimuth   @ Wa^T + ba)           [8,512]
//   out[2] = relu(relu(elev @ We^T + be) + s*proj_b), s = 0.4*sigmoid(residual_gain)
//
// The 133 MB receive_spikes tensor and the 85-step scan never influence the output.
//
// Implementation: one warp per output element (3*8*512 = 12288 warps).
// Each lane loads 8 consecutive K-elements via two float4 loads (fully coalesced
// across the warp for the weight row; the activation row is shared by 512 warps
// and served from L1/L2), then a 5-step shfl-xor reduction.

#define HID 512
#define KDIM 256
#define BATCH 8
#define N_OUT (3 * BATCH * HID)   // 12288

__global__ __launch_bounds__(256) void enc_out_kernel(
    const float* __restrict__ distance,
    const float* __restrict__ azimuth,
    const float* __restrict__ elevation,
    const float* __restrict__ Wd, const float* __restrict__ bd,
    const float* __restrict__ Wa, const float* __restrict__ ba,
    const float* __restrict__ We, const float* __restrict__ be,
    const float* __restrict__ proj_b,
    const float* __restrict__ residual_gain,
    float* __restrict__ out)
{
    const int gwarp = (blockIdx.x * blockDim.x + threadIdx.x) >> 5;
    const int lane  = threadIdx.x & 31;
    if (gwarp >= N_OUT) return;

    const int m = gwarp >> 12;        // 0..2  (4096 outputs per matrix)
    const int r = gwarp & 4095;
    const int b = r >> 9;             // 0..7
    const int j = r & (HID - 1);      // 0..511

    const float* x;
    const float* W;
    const float* bias;
    if (m == 0)      { x = distance;  W = Wd; bias = bd; }
    else if (m == 1) { x = azimuth;   W = Wa; bias = ba; }
    else             { x = elevation; W = We; bias = be; }

    // Each lane covers k in [lane*8, lane*8+8) -> 32 lanes * 8 = 256 = KDIM.
    const float4* xv = reinterpret_cast<const float4*>(x + b * KDIM) + lane * 2;
    const float4* wv = reinterpret_cast<const float4*>(W + (size_t)j * KDIM) + lane * 2;

    const float4 x0 = xv[0];
    const float4 x1 = xv[1];
    const float4 w0 = wv[0];
    const float4 w1 = wv[1];

    float s = x0.x * w0.x;
    s = fmaf(x0.y, w0.y, s);
    s = fmaf(x0.z, w0.z, s);
    s = fmaf(x0.w, w0.w, s);
    s = fmaf(x1.x, w1.x, s);
    s = fmaf(x1.y, w1.y, s);
    s = fmaf(x1.z, w1.z, s);
    s = fmaf(x1.w, w1.w, s);

    #pragma unroll
    for (int off = 16; off; off >>= 1)
        s += __shfl_xor_sync(0xffffffffu, s, off);

    if (lane == 0) {
        float v = s + bias[j];
        v = fmaxf(v, 0.0f);  // relu: final for m=0,1; base_e for m=2
        if (m == 2) {
            const float g = residual_gain[0];
            const float scale = 0.4f / (1.0f + expf(-g));
            // pooled spikes == 0  =>  residual == proj_b (proven above)
            v = fmaxf(fmaf(scale, proj_b[j], v), 0.0f);
        }
        out[gwarp] = v;   // out index == m*4096 + b*512 + j == gwarp
    }
}

extern "C" void kernel_launch(void* const* d_in, const int* in_sizes, int n_in,
                              void* d_out, int out_size)
{
    // metadata order:
    // 0 distance [8,256]      1 azimuth [8,256]     2 elevation [8,256]
    // 3 receive_spikes        4 spike_count         5 Wd [512,256]  6 bd [512]
    // 7 Wa [512,256]          8 ba [512]            9 We [512,256] 10 be [512]
    // 11 conv_W              12 conv_b             13 proj_W       14 proj_b [512]
    // 15 residual_gain [1]
    (void)in_sizes; (void)n_in;
    const float* distance  = (const float*)d_in[0];
    const float* azimuth   = (const float*)d_in[1];
    const float* elevation = (const float*)d_in[2];
    const float* Wd        = (const float*)d_in[5];
    const float* bd        = (const float*)d_in[6];
    const float* Wa        = (const float*)d_in[7];
    const float* ba        = (const float*)d_in[8];
    const float* We        = (const float*)d_in[9];
    const float* be        = (const float*)d_in[10];
    const float* proj_b    = (const float*)d_in[14];
    const float* gain      = (const float*)d_in[15];
    float* out = (float*)d_out;
    (void)out_size;

    const int threads = 256;
    const int warps_per_block = threads / 32;
    const int blocks = (N_OUT + warps_per_block - 1) / warps_per_block;  // 1536
    enc_out_kernel<<<blocks, threads>>>(distance, azimuth, elevation,
                                        Wd, bd, Wa, ba, We, be,
                                        proj_b, gain, out);
}

// round 2
// speedup vs baseline: 1.1991x; 1.1991x over previous
#include <cuda_runtime.h>
#include <cuda_bf16.h>
#include <math.h>

// ElevationSConvResidualEncoder — GB300 sm_103a
//
// Dead-code proof (round 0, confirmed by rel_err=2e-7):
//   mem = sigmoid(o)*tanh(syn) <= 1.0 always  =>  spike = (mem-1 > 0) == 0 always
//   => pooled == 0 => residual == proj_b
//   => out[0] = relu(distance @ Wd^T + bd)
//      out[1] = relu(azimuth  @ Wa^T + ba)
//      out[2] = relu(relu(elev @ We^T + be) + 0.4*sigmoid(gain)*proj_b)
//
// Round-2 shape: one warp per (matrix m, output j) — 1536 warps total.
// Each warp loads its W row ONCE (2 float4/lane) plus all 8 batch x-rows
// (16 float4/lane, L1-hot broadcast across the 512 warps of the same matrix),
// giving MLP ~18 independent loads in flight per lane before any dependency.
// Then 8 dot-product accumulators and 8 interleaved 5-step butterfly reductions.
// W traffic from DRAM: exactly 1.57 MB, read once.

#define HID 512
#define KDIM 256
#define BATCH 8
#define N_TASK (3 * HID)          // 1536 warp-tasks
#define WARPS_PER_BLOCK 4
#define THREADS (WARPS_PER_BLOCK * 32)

__global__ __launch_bounds__(THREADS) void enc_out_kernel(
    const float* __restrict__ distance,
    const float* __restrict__ azimuth,
    const float* __restrict__ elevation,
    const float* __restrict__ Wd, const float* __restrict__ bd,
    const float* __restrict__ Wa, const float* __restrict__ ba,
    const float* __restrict__ We, const float* __restrict__ be,
    const float* __restrict__ proj_b,
    const float* __restrict__ residual_gain,
    float* __restrict__ out)
{
    const int gwarp = blockIdx.x * WARPS_PER_BLOCK + (threadIdx.x >> 5);
    const int lane  = threadIdx.x & 31;
    if (gwarp >= N_TASK) return;

    const int m = gwarp >> 9;          // 0..2
    const int j = gwarp & (HID - 1);   // 0..511

    const float* x;
    const float* W;
    const float* bias;
    if (m == 0)      { x = distance;  W = Wd; bias = bd; }
    else if (m == 1) { x = azimuth;   W = Wa; bias = ba; }
    else             { x = elevation; W = We; bias = be; }

    // Lane covers k in [lane*8, lane*8+8).
    const float4* wv = reinterpret_cast<const float4*>(W + (size_t)j * KDIM) + lane * 2;
    const float4 w0 = wv[0];
    const float4 w1 = wv[1];

    // Front-load all 8 batches' x segments (independent loads -> high MLP).
    float4 xs0[BATCH], xs1[BATCH];
    #pragma unroll
    for (int b = 0; b < BATCH; b++) {
        const float4* xv = reinterpret_cast<const float4*>(x + b * KDIM) + lane * 2;
        xs0[b] = xv[0];
        xs1[b] = xv[1];
    }

    float acc[BATCH];
    #pragma unroll
    for (int b = 0; b < BATCH; b++) {
        float s = xs0[b].x * w0.x;
        s = fmaf(xs0[b].y, w0.y, s);
        s = fmaf(xs0[b].z, w0.z, s);
        s = fmaf(xs0[b].w, w0.w, s);
        s = fmaf(xs1[b].x, w1.x, s);
        s = fmaf(xs1[b].y, w1.y, s);
        s = fmaf(xs1[b].z, w1.z, s);
        s = fmaf(xs1[b].w, w1.w, s);
        acc[b] = s;
    }

    // 8 interleaved butterfly reductions (independent shfl chains pipeline).
    #pragma unroll
    for (int off = 16; off; off >>= 1) {
        #pragma unroll
        for (int b = 0; b < BATCH; b++)
            acc[b] += __shfl_xor_sync(0xffffffffu, acc[b], off);
    }

    if (lane == 0) {
        const float bj = bias[j];
        float addj = 0.0f;
        if (m == 2) {
            const float g = residual_gain[0];
            addj = (0.4f / (1.0f + expf(-g))) * proj_b[j];
        }
        float* o = out + ((size_t)m << 12) + j;   // out[m][b][j], b-stride 512
        #pragma unroll
        for (int b = 0; b < BATCH; b++) {
            float v = fmaxf(acc[b] + bj, 0.0f);
            if (m == 2) v = fmaxf(v + addj, 0.0f);
            o[b * HID] = v;
        }
    }
}

extern "C" void kernel_launch(void* const* d_in, const int* in_sizes, int n_in,
                              void* d_out, int out_size)
{
    // metadata order:
    // 0 distance 1 azimuth 2 elevation 3 receive_spikes 4 spike_count
    // 5 Wd 6 bd 7 Wa 8 ba 9 We 10 be 11 conv_W 12 conv_b 13 proj_W 14 proj_b
    // 15 residual_gain
    (void)in_sizes; (void)n_in; (void)out_size;
    const float* distance  = (const float*)d_in[0];
    const float* azimuth   = (const float*)d_in[1];
    const float* elevation = (const float*)d_in[2];
    const float* Wd        = (const float*)d_in[5];
    const float* bd        = (const float*)d_in[6];
    const float* Wa        = (const float*)d_in[7];
    const float* ba        = (const float*)d_in[8];
    const float* We        = (const float*)d_in[9];
    const float* be        = (const float*)d_in[10];
    const float* proj_b    = (const float*)d_in[14];
    const float* gain      = (const float*)d_in[15];
    float* out = (float*)d_out;

    const int blocks = (N_TASK + WARPS_PER_BLOCK - 1) / WARPS_PER_BLOCK;  // 384
    enc_out_kernel<<<blocks, THREADS>>>(distance, azimuth, elevation,
                                        Wd, bd, Wa, ba, We, be,
                                        proj_b, gain, out);
}

// round 3
// speedup vs baseline: 1.2512x; 1.0435x over previous
#include <cuda_runtime.h>
#include <cuda_bf16.h>
#include <math.h>

// ElevationSConvResidualEncoder — GB300 sm_103a
//
// Dead-code proof (round 0, confirmed rel_err=2e-7):
//   mem = sigmoid(o)*tanh(syn) <= 1.0 always => spike == 0 always
//   => pooled == 0 => residual == proj_b
//   => out[0] = relu(distance @ Wd^T + bd)
//      out[1] = relu(azimuth  @ Wa^T + ba)
//      out[2] = relu(relu(elev @ We^T + be) + 0.4*sigmoid(gain)*proj_b)
//
// Round-3 shape: duration is launch-overhead + one memory round-trip + tail.
// Minimize the tail: warp per (m, j, batch-pair) -> 6144 warps (single wave),
// 6 LDG.128/lane, 16 FMA, 2 interleaved butterfly reductions. All scalar
// dependencies (bias[j], proj_b[j], gain, expf) hoisted to kernel start so
// nothing memory-dependent remains after the shfl reduction.

#define HID 512
#define KDIM 256
#define N_WARP (3 * HID * 4)      // 6144 warp-tasks (2 batches each)
#define THREADS 512               // 16 warps/block -> 384 blocks

__global__ __launch_bounds__(THREADS) void enc_out_kernel(
    const float* __restrict__ distance,
    const float* __restrict__ azimuth,
    const float* __restrict__ elevation,
    const float* __restrict__ Wd, const float* __restrict__ bd,
    const float* __restrict__ Wa, const float* __restrict__ ba,
    const float* __restrict__ We, const float* __restrict__ be,
    const float* __restrict__ proj_b,
    const float* __restrict__ residual_gain,
    float* __restrict__ out)
{
    const int gwarp = blockIdx.x * (THREADS / 32) + (threadIdx.x >> 5);
    const int lane  = threadIdx.x & 31;

    const int m  = gwarp >> 11;          // 0..2   (2048 warps per matrix)
    const int r  = gwarp & 2047;
    const int j  = r >> 2;               // 0..511
    const int t  = r & 3;                // batch pair index
    const int b0 = t * 2;                // batches b0, b0+1

    const float* x;
    const float* W;
    const float* bias;
    if (m == 0)      { x = distance;  W = Wd; bias = bd; }
    else if (m == 1) { x = azimuth;   W = Wa; bias = ba; }
    else             { x = elevation; W = We; bias = be; }

    // ---- issue ALL loads up front (single memory-latency exposure) ----
    const float4* wv  = reinterpret_cast<const float4*>(W + (size_t)j * KDIM) + lane * 2;
    const float4* xva = reinterpret_cast<const float4*>(x + (size_t)b0 * KDIM) + lane * 2;
    const float4* xvb = xva + (KDIM / 4);   // batch b0+1

    const float4 w0 = wv[0];
    const float4 w1 = wv[1];
    const float4 a0 = xva[0];
    const float4 a1 = xva[1];
    const float4 c0 = xvb[0];
    const float4 c1 = xvb[1];

    // Scalar tail dependencies, hoisted: issue now, overlap with vector waits.
    const float bj = bias[j];
    float addj = 0.0f;
    if (m == 2) {
        const float g = residual_gain[0];
        addj = (0.4f / (1.0f + expf(-g))) * proj_b[j];   // MUFU overlaps mem wait
    }

    // ---- 16 FMA, two accumulators ----
    float sa = a0.x * w0.x;
    float sb = c0.x * w0.x;
    sa = fmaf(a0.y, w0.y, sa);  sb = fmaf(c0.y, w0.y, sb);
    sa = fmaf(a0.z, w0.z, sa);  sb = fmaf(c0.z, w0.z, sb);
    sa = fmaf(a0.w, w0.w, sa);  sb = fmaf(c0.w, w0.w, sb);
    sa = fmaf(a1.x, w1.x, sa);  sb = fmaf(c1.x, w1.x, sb);
    sa = fmaf(a1.y, w1.y, sa);  sb = fmaf(c1.y, w1.y, sb);
    sa = fmaf(a1.z, w1.z, sa);  sb = fmaf(c1.z, w1.z, sb);
    sa = fmaf(a1.w, w1.w, sa);  sb = fmaf(c1.w, w1.w, sb);

    // ---- two interleaved 5-step butterflies ----
    #pragma unroll
    for (int off = 16; off; off >>= 1) {
        sa += __shfl_xor_sync(0xffffffffu, sa, off);
        sb += __shfl_xor_sync(0xffffffffu, sb, off);
    }

    if (lane == 0) {
        float va = fmaxf(sa + bj, 0.0f);
        float vb = fmaxf(sb + bj, 0.0f);
        if (m == 2) {
            va = fmaxf(va + addj, 0.0f);
            vb = fmaxf(vb + addj, 0.0f);
        }
        float* o = out + ((size_t)m << 12) + (size_t)b0 * HID + j;
        o[0]   = va;
        o[HID] = vb;
    }
}

extern "C" void kernel_launch(void* const* d_in, const int* in_sizes, int n_in,
                              void* d_out, int out_size)
{
    // metadata order:
    // 0 distance 1 azimuth 2 elevation 3 receive_spikes 4 spike_count
    // 5 Wd 6 bd 7 Wa 8 ba 9 We 10 be 11 conv_W 12 conv_b 13 proj_W 14 proj_b
    // 15 residual_gain
    (void)in_sizes; (void)n_in; (void)out_size;
    const float* distance  = (const float*)d_in[0];
    const float* azimuth   = (const float*)d_in[1];
    const float* elevation = (const float*)d_in[2];
    const float* Wd        = (const float*)d_in[5];
    const float* bd        = (const float*)d_in[6];
    const float* Wa        = (const float*)d_in[7];
    const float* ba        = (const float*)d_in[8];
    const float* We        = (const float*)d_in[9];
    const float* be        = (const float*)d_in[10];
    const float* proj_b    = (const float*)d_in[14];
    const float* gain      = (const float*)d_in[15];
    float* out = (float*)d_out;

    const int blocks = N_WARP / (THREADS / 32);   // 384
    enc_out_kernel<<<blocks, THREADS>>>(distance, azimuth, elevation,
                                        Wd, bd, Wa, ba, We, be,
                                        proj_b, gain, out);
}